// round 9
// baseline (speedup 1.0000x reference)
#include <cuda_runtime.h>
#include <cuda_bf16.h>
#include <math.h>
#include <stdint.h>

// Problem dims (fixed by setup_inputs)
#define Bn 2
#define Sn 2048
#define Hn 1024
#define NHn 16
#define BHn 32        // Bn*NHn
#define NT 8          // series terms n=0..7
#define KT 128        // NHn*NT — GEMM N/K
#define KSn 8         // k-split chunks for k_Tg (8 x 256)

// ---------------- scratch (device globals; no allocations allowed) ----------
__device__ float g_wbar[32 * Hn];
__device__ float g_bbar[32];
__device__ float g_qm[BHn * Sn];                        // [bh][s]
__device__ __align__(16) __nv_bfloat16 g_Pt[Bn * KT * Sn];   // [b][col][k] bf16
__device__ __align__(16) __nv_bfloat16 g_hsT[(size_t)Bn * Hn * Sn]; // [b][j][k] bf16
__device__ float g_Tp[KSn * Bn * Hn * KT];              // partial T fp32
__device__ float g_T[Bn * Hn * KT];                     // [b][j][col]
__device__ float g_z[Bn * KT];                          // [b][h*8+n]
__device__ __align__(16) __nv_bfloat16 g_Ut[Bn * Hn * KT];   // [b][e][col] bf16

__constant__ float c_invf[NT] = {1.f, 1.f, 0.5f, 1.f/6.f, 1.f/24.f, 1.f/120.f,
                                 1.f/720.f, 1.f/5040.f};

// ---------------- warp-level bf16 MMA (sm_80+ baseline; ok on sm_103) -------
__device__ __forceinline__ void mma16816(float* d, const uint32_t* a, const uint32_t* b) {
    asm volatile(
        "mma.sync.aligned.m16n8k16.row.col.f32.bf16.bf16.f32 "
        "{%0,%1,%2,%3}, {%4,%5,%6,%7}, {%8,%9}, {%0,%1,%2,%3};"
        : "+f"(d[0]), "+f"(d[1]), "+f"(d[2]), "+f"(d[3])
        : "r"(a[0]), "r"(a[1]), "r"(a[2]), "r"(a[3]), "r"(b[0]), "r"(b[1]));
}
__device__ __forceinline__ uint32_t bf2u(float a, float b) {
    __nv_bfloat162 h2;
    h2.x = __float2bfloat16_rn(a);
    h2.y = __float2bfloat16_rn(b);
    return *(uint32_t*)&h2;
}

// ---------------- K1: fold Wq/Wk rows into per-head means ----------------
__global__ void k_bar(const float* __restrict__ Wq, const float* __restrict__ Wk,
                      const float* __restrict__ bq, const float* __restrict__ bk) {
    int idx = blockIdx.x * blockDim.x + threadIdx.x;
    if (idx < 32 * Hn) {
        int o = idx >> 10, k = idx & (Hn - 1);
        const float* W = (o < 16) ? Wq : Wk;
        int h = o & 15;
        float s = 0.f;
        #pragma unroll 4
        for (int d = 0; d < 64; d++) s += W[(h * 64 + d) * Hn + k];
        g_wbar[o * Hn + k] = s * (1.f / 64.f);
    }
    if (idx < 32) {
        const float* bb = (idx < 16) ? bq : bk;
        int h = idx & 15;
        float s = 0.f;
        for (int d = 0; d < 64; d++) s += bb[h * 64 + d];
        g_bbar[idx] = s * (1.f / 64.f);
    }
}

// ---------------- K2: qm/km via mma.sync (32 rows/block, N=32, K=1024) ------
// smem: sA bf16[32][1032] (hs rows), sW bf16[32][1032] (wbar), sRed f32[4][32][34]
#define QPAD 1032
__global__ void __launch_bounds__(256) k_qkm(const float* __restrict__ hs,
                                             const float* __restrict__ mask) {
    extern __shared__ __align__(16) char qsm[];
    __nv_bfloat16* sA = (__nv_bfloat16*)qsm;                    // 66048 B
    __nv_bfloat16* sW = (__nv_bfloat16*)(qsm + 66048);          // 66048 B
    float (*sRed)[32][34] = (float (*)[32][34])(qsm + 132096);  // 17408 B

    int t = threadIdx.x;
    int rb = blockIdx.x * 32;

    // stage hs rows + wbar, converting fp32 -> bf16
    {
        int row = t >> 3, cb = (t & 7) * 128;
        const float* hrow = hs + (size_t)(rb + row) * Hn + cb;
        const float* wrow = g_wbar + (size_t)row * Hn + cb;
        #pragma unroll
        for (int q = 0; q < 32; q++) {
            float4 v = *(const float4*)(hrow + q * 4);
            float4 w = *(const float4*)(wrow + q * 4);
            *(uint2*)&sA[row * QPAD + cb + q * 4] =
                make_uint2(bf2u(v.x, v.y), bf2u(v.z, v.w));
            *(uint2*)&sW[row * QPAD + cb + q * 4] =
                make_uint2(bf2u(w.x, w.y), bf2u(w.z, w.w));
        }
    }
    __syncthreads();

    int wid = t >> 5, lane = t & 31, g = lane >> 2, tg = lane & 3;
    int kseg = wid >> 1, mh = wid & 1;
    int r0 = mh * 16 + g;

    float acc[4][4];
    #pragma unroll
    for (int ni = 0; ni < 4; ni++)
        #pragma unroll
        for (int q = 0; q < 4; q++) acc[ni][q] = 0.f;

    #pragma unroll 4
    for (int ks = 0; ks < 16; ks++) {
        int k0 = kseg * 256 + ks * 16;
        uint32_t a[4];
        a[0] = *(const uint32_t*)(sA + r0 * QPAD + k0 + 2 * tg);
        a[1] = *(const uint32_t*)(sA + (r0 + 8) * QPAD + k0 + 2 * tg);
        a[2] = *(const uint32_t*)(sA + r0 * QPAD + k0 + 8 + 2 * tg);
        a[3] = *(const uint32_t*)(sA + (r0 + 8) * QPAD + k0 + 8 + 2 * tg);
        #pragma unroll
        for (int ni = 0; ni < 4; ni++) {
            uint32_t bb[2];
            bb[0] = *(const uint32_t*)(sW + (ni * 8 + g) * QPAD + k0 + 2 * tg);
            bb[1] = *(const uint32_t*)(sW + (ni * 8 + g) * QPAD + k0 + 8 + 2 * tg);
            mma16816(acc[ni], a, bb);
        }
    }

    // write k-segment partials
    #pragma unroll
    for (int ni = 0; ni < 4; ni++) {
        *(float2*)&sRed[kseg][mh * 16 + g][ni * 8 + 2 * tg] =
            make_float2(acc[ni][0], acc[ni][1]);
        *(float2*)&sRed[kseg][mh * 16 + g + 8][ni * 8 + 2 * tg] =
            make_float2(acc[ni][2], acc[ni][3]);
    }
    __syncthreads();

    // reduce 4 k-segments + epilogue (qm / Pt powers)
    int row = t >> 3, og = (t & 7) * 4;
    int rg = rb + row;
    int b = rg >> 11, s = rg & (Sn - 1);
    float v4[4];
    #pragma unroll
    for (int j = 0; j < 4; j++) {
        int o = og + j;
        v4[j] = sRed[0][row][o] + sRed[1][row][o] + sRed[2][row][o] + sRed[3][row][o]
              + g_bbar[o];
    }
    if (og < 16) {
        #pragma unroll
        for (int j = 0; j < 4; j++)
            g_qm[(b * NHn + og + j) * Sn + s] = v4[j];
    } else {
        float mk = (mask[b * Sn + s] > 0.f) ? 1.f : 0.f;
        #pragma unroll
        for (int j = 0; j < 4; j++) {
            int h = (og + j) & 15;
            float km = v4[j];
            float p = mk;
            __nv_bfloat16* dst = g_Pt + (size_t)(b * KT + h * 8) * Sn + s;
            #pragma unroll
            for (int n = 0; n < NT; n++) {
                dst[(size_t)n * Sn] = __float2bfloat16_rn(p);
                p *= km;
            }
        }
    }
}

// ---------------- K3: transpose hs -> g_hsT bf16 [b][j][k] ----------------
__global__ void __launch_bounds__(256) k_tr(const float* __restrict__ hs) {
    __shared__ float sm[64][33];
    int t = threadIdx.x;
    int k0 = blockIdx.x * 64, j0 = blockIdx.y * 32, b = blockIdx.z;
    #pragma unroll
    for (int i = 0; i < 2; i++) {
        int idx = t + 256 * i;
        int k = idx >> 3, jq = (idx & 7) * 4;
        float4 v = *(const float4*)&hs[(size_t)(b * Sn + k0 + k) * Hn + j0 + jq];
        sm[k][jq + 0] = v.x; sm[k][jq + 1] = v.y; sm[k][jq + 2] = v.z; sm[k][jq + 3] = v.w;
    }
    __syncthreads();
    int jj = t >> 3, c = t & 7;
    uint32_t w[4];
    #pragma unroll
    for (int q = 0; q < 4; q++)
        w[q] = bf2u(sm[c * 8 + q * 2 + 0][jj], sm[c * 8 + q * 2 + 1][jj]);
    *(uint4*)(g_hsT + ((size_t)(b * Hn + j0 + jj)) * Sn + k0 + c * 8) =
        make_uint4(w[0], w[1], w[2], w[3]);
}

// ---------------- K4: z[b][col] = sum_k Pt[b][col][k] (1 col/block) ---------
__global__ void __launch_bounds__(128) k_z() {
    int col = blockIdx.x, b = blockIdx.y;
    int t = threadIdx.x;
    const __nv_bfloat16* src = g_Pt + (size_t)(b * KT + col) * Sn;
    float s = 0.f;
    #pragma unroll
    for (int half = 0; half < 2; half++) {
        uint4 v = *(const uint4*)(src + half * 1024 + t * 8);
        uint32_t u[4] = {v.x, v.y, v.z, v.w};
        #pragma unroll
        for (int q = 0; q < 4; q++) {
            float2 f = __bfloat1622float2(*(__nv_bfloat162*)&u[q]);
            s += f.x + f.y;
        }
    }
    #pragma unroll
    for (int off = 16; off; off >>= 1) s += __shfl_xor_sync(0xffffffffu, s, off);
    __shared__ float ws[4];
    if ((t & 31) == 0) ws[t >> 5] = s;
    __syncthreads();
    if (t == 0) g_z[b * KT + col] = ws[0] + ws[1] + ws[2] + ws[3];
}

// ---------------- K5: T-GEMM via mma.sync: Tp = hsT @ Pt^T (128x128x256) ----
#define PAD 264
__global__ void __launch_bounds__(256) k_Tg() {
    extern __shared__ __align__(16) __nv_bfloat16 smem[];
    __nv_bfloat16* sA = smem;               // [128][264]
    __nv_bfloat16* sB = smem + 128 * PAD;   // [128][264]
    int t = threadIdx.x;
    int jt = blockIdx.x, kc = blockIdx.y, b = blockIdx.z;
    int k0g = kc * 256;

    const __nv_bfloat16* Asrc = g_hsT + ((size_t)(b * Hn + jt * 128)) * Sn + k0g;
    const __nv_bfloat16* Bsrc = g_Pt + ((size_t)(b * KT)) * Sn + k0g;
    #pragma unroll
    for (int i = 0; i < 16; i++) {
        int idx = t + 256 * i;
        int m = idx >> 5, c = idx & 31;
        *(uint4*)(sA + m * PAD + c * 8) = *(const uint4*)(Asrc + (size_t)m * Sn + c * 8);
        *(uint4*)(sB + m * PAD + c * 8) = *(const uint4*)(Bsrc + (size_t)m * Sn + c * 8);
    }
    __syncthreads();

    int wid = t >> 5, lane = t & 31;
    int wm = wid >> 1, wn = wid & 1;
    int R = wm * 32, Cb = wn * 64;
    int g = lane >> 2, tg = lane & 3;

    float acc[2][8][4];
    #pragma unroll
    for (int mi = 0; mi < 2; mi++)
        #pragma unroll
        for (int ni = 0; ni < 8; ni++)
            #pragma unroll
            for (int q = 0; q < 4; q++) acc[mi][ni][q] = 0.f;

    #pragma unroll 4
    for (int ks = 0; ks < 16; ks++) {
        int k0 = ks * 16;
        uint32_t a[2][4];
        #pragma unroll
        for (int mi = 0; mi < 2; mi++) {
            int r0 = R + mi * 16 + g;
            a[mi][0] = *(const uint32_t*)(sA + r0 * PAD + k0 + 2 * tg);
            a[mi][1] = *(const uint32_t*)(sA + (r0 + 8) * PAD + k0 + 2 * tg);
            a[mi][2] = *(const uint32_t*)(sA + r0 * PAD + k0 + 8 + 2 * tg);
            a[mi][3] = *(const uint32_t*)(sA + (r0 + 8) * PAD + k0 + 8 + 2 * tg);
        }
        #pragma unroll
        for (int ni = 0; ni < 8; ni++) {
            int n = Cb + ni * 8 + g;
            uint32_t bb[2];
            bb[0] = *(const uint32_t*)(sB + n * PAD + k0 + 2 * tg);
            bb[1] = *(const uint32_t*)(sB + n * PAD + k0 + 8 + 2 * tg);
            mma16816(acc[0][ni], a[0], bb);
            mma16816(acc[1][ni], a[1], bb);
        }
    }

    #pragma unroll
    for (int mi = 0; mi < 2; mi++) {
        int j = jt * 128 + R + mi * 16 + g;
        float* base = g_Tp + ((size_t)((kc * Bn + b) * Hn + j)) * KT;
        #pragma unroll
        for (int ni = 0; ni < 8; ni++) {
            int col = Cb + ni * 8 + 2 * tg;
            *(float2*)(base + col) = make_float2(acc[mi][ni][0], acc[mi][ni][1]);
            *(float2*)(base + 8 * KT + col) = make_float2(acc[mi][ni][2], acc[mi][ni][3]);
        }
    }
}

// ---------------- K6: reduce T partials (deterministic, float4) -------------
__global__ void __launch_bounds__(256) k_Tred() {
    int idx = blockIdx.x * 256 + threadIdx.x;
    const float4* src = (const float4*)g_Tp;
    float4 s = src[idx];
    #pragma unroll
    for (int kc = 1; kc < KSn; kc++) {
        float4 v = src[(size_t)kc * (Bn * Hn * KT / 4) + idx];
        s.x += v.x; s.y += v.y; s.z += v.z; s.w += v.w;
    }
    ((float4*)g_T)[idx] = s;
}

// ---------------- K7: Ut[b][e][h*8+n] = bf16(((T@Wv_h^T)+z*bv_h)@Wo_h^T) ----
__global__ void __launch_bounds__(256) k_U(const float* __restrict__ Wv,
                                           const float* __restrict__ bv,
                                           const float* __restrict__ Wo) {
    int bh = blockIdx.x, b = bh >> 4, h = bh & 15;
    int eq = blockIdx.y;
    __shared__ float Ts[NT][Hn];
    __shared__ float Ms[NT][64];
    int t = threadIdx.x;
    #pragma unroll
    for (int i = 0; i < 4; i++) {
        int j = t + 256 * i;
        const float* src = g_T + (((size_t)(b * Hn + j)) << 7) + h * 8;
        float4 v0 = *(const float4*)src;
        float4 v1 = *(const float4*)(src + 4);
        Ts[0][j] = v0.x; Ts[1][j] = v0.y; Ts[2][j] = v0.z; Ts[3][j] = v0.w;
        Ts[4][j] = v1.x; Ts[5][j] = v1.y; Ts[6][j] = v1.z; Ts[7][j] = v1.w;
    }
    float zl[NT];
    #pragma unroll
    for (int n = 0; n < NT; n++) zl[n] = g_z[b * KT + h * 8 + n];
    __syncthreads();

    int d = t >> 2, part = t & 3;
    float pn[NT] = {};
    const float* wv = Wv + (size_t)(h * 64 + d) * Hn + part * 256;
    for (int jj = 0; jj < 256; jj += 4) {
        float4 w4 = *(const float4*)(wv + jj);
        int jb = part * 256 + jj;
        #pragma unroll
        for (int n = 0; n < NT; n++) {
            float4 t4 = *(const float4*)&Ts[n][jb];
            pn[n] += w4.x * t4.x + w4.y * t4.y + w4.z * t4.z + w4.w * t4.w;
        }
    }
    #pragma unroll
    for (int n = 0; n < NT; n++) {
        pn[n] += __shfl_xor_sync(0xffffffffu, pn[n], 1);
        pn[n] += __shfl_xor_sync(0xffffffffu, pn[n], 2);
    }
    if (part == 0) {
        float bvd = bv[h * 64 + d];
        #pragma unroll
        for (int n = 0; n < NT; n++) Ms[n][d] = pn[n] + zl[n] * bvd;
    }
    __syncthreads();

    int e = eq * 256 + t;
    float u[NT] = {};
    const float* wo = Wo + (size_t)e * Hn + h * 64;
    #pragma unroll 4
    for (int dd = 0; dd < 64; dd += 4) {
        float4 w4 = *(const float4*)(wo + dd);
        #pragma unroll
        for (int n = 0; n < NT; n++)
            u[n] += w4.x * Ms[n][dd] + w4.y * Ms[n][dd+1]
                  + w4.z * Ms[n][dd+2] + w4.w * Ms[n][dd+3];
    }
    uint32_t w[4];
    #pragma unroll
    for (int q = 0; q < 4; q++)
        w[q] = bf2u(u[q * 2 + 0], u[q * 2 + 1]);
    *(uint4*)(g_Ut + ((size_t)(b * Hn + e)) * KT + h * 8) = make_uint4(w[0], w[1], w[2], w[3]);
}

// ---------------- K8: out = coef@Ut^T + bo + hs via mma.sync (128x128x128) --
#define PADC 136
__global__ void __launch_bounds__(256) k_comb(const float* __restrict__ bo,
                                              const float* __restrict__ hs,
                                              float* __restrict__ out) {
    extern __shared__ __align__(16) __nv_bfloat16 smemc[];
    __nv_bfloat16* sA = smemc;                // coef [128][136]
    __nv_bfloat16* sB = smemc + 128 * PADC;   // Ut   [128][136]
    __shared__ float zs[KT];

    int t = threadIdx.x;
    int bn = blockIdx.x, bm = blockIdx.y;
    int b = bm >> 4;
    int sbase = (bm & 15) * 128;

    if (t < KT) zs[t] = g_z[b * KT + t];

    #pragma unroll
    for (int i = 0; i < 8; i++) {
        int idx = t + 256 * i;
        int row = idx >> 4, c = idx & 15;
        *(uint4*)(sB + row * PADC + c * 8) =
            *(const uint4*)(g_Ut + ((size_t)(b * Hn + bn * 128 + row)) * KT + c * 8);
    }
    __syncthreads();   // zs visible

    {
        int m = t >> 1, hbase = (t & 1) * 8;
        int s = sbase + m;
        #pragma unroll
        for (int hh = 0; hh < 8; hh++) {
            int h = hbase + hh;
            float a = g_qm[(size_t)(b * NHn + h) * Sn + s];
            float c[NT], p = 1.f, den = 0.f;
            #pragma unroll
            for (int n = 0; n < NT; n++) {
                c[n] = p * c_invf[n];
                den += c[n] * zs[h * 8 + n];
                p *= a;
            }
            float inv = (den > 0.f) ? 1.f / den : 0.f;
            uint32_t wv[4];
            #pragma unroll
            for (int q = 0; q < 4; q++)
                wv[q] = bf2u(c[q * 2 + 0] * inv, c[q * 2 + 1] * inv);
            *(uint4*)(sA + m * PADC + h * 8) = make_uint4(wv[0], wv[1], wv[2], wv[3]);
        }
    }
    __syncthreads();

    int wid = t >> 5, lane = t & 31;
    int wm = wid >> 1, wn = wid & 1;
    int R = wm * 32, Cb = wn * 64;
    int g = lane >> 2, tg = lane & 3;

    float acc[2][8][4];
    #pragma unroll
    for (int mi = 0; mi < 2; mi++)
        #pragma unroll
        for (int ni = 0; ni < 8; ni++)
            #pragma unroll
            for (int q = 0; q < 4; q++) acc[mi][ni][q] = 0.f;

    #pragma unroll
    for (int ks = 0; ks < 8; ks++) {
        int k0 = ks * 16;
        uint32_t a[2][4];
        #pragma unroll
        for (int mi = 0; mi < 2; mi++) {
            int r0 = R + mi * 16 + g;
            a[mi][0] = *(const uint32_t*)(sA + r0 * PADC + k0 + 2 * tg);
            a[mi][1] = *(const uint32_t*)(sA + (r0 + 8) * PADC + k0 + 2 * tg);
            a[mi][2] = *(const uint32_t*)(sA + r0 * PADC + k0 + 8 + 2 * tg);
            a[mi][3] = *(const uint32_t*)(sA + (r0 + 8) * PADC + k0 + 8 + 2 * tg);
        }
        #pragma unroll
        for (int ni = 0; ni < 8; ni++) {
            int n = Cb + ni * 8 + g;
            uint32_t bb[2];
            bb[0] = *(const uint32_t*)(sB + n * PADC + k0 + 2 * tg);
            bb[1] = *(const uint32_t*)(sB + n * PADC + k0 + 8 + 2 * tg);
            mma16816(acc[0][ni], a[0], bb);
            mma16816(acc[1][ni], a[1], bb);
        }
    }

    #pragma unroll
    for (int mi = 0; mi < 2; mi++) {
        #pragma unroll
        for (int half = 0; half < 2; half++) {
            int row = bm * 128 + R + mi * 16 + g + half * 8;
            const float* hp = hs + (size_t)row * Hn;
            float* op = out + (size_t)row * Hn;
            #pragma unroll
            for (int ni = 0; ni < 8; ni++) {
                int col = bn * 128 + Cb + ni * 8 + 2 * tg;
                float2 h2 = *(const float2*)(hp + col);
                float2 b2 = *(const float2*)(bo + col);
                float d0 = acc[mi][ni][half * 2 + 0] + h2.x + b2.x;
                float d1 = acc[mi][ni][half * 2 + 1] + h2.y + b2.y;
                *(float2*)(op + col) = make_float2(d0, d1);
            }
        }
    }
}

// ---------------- K9: LayerNorm, warp-per-row (8 rows/block) ----------------
__global__ void __launch_bounds__(256) k_ln(float* __restrict__ x,
                                            const float* __restrict__ w,
                                            const float* __restrict__ bgam) {
    int wrp = threadIdx.x >> 5, l = threadIdx.x & 31;
    int row = blockIdx.x * 8 + wrp;
    float* p = x + (size_t)row * Hn;
    float4 v[8];
    float s = 0.f, q2 = 0.f;
    #pragma unroll
    for (int i = 0; i < 8; i++) {
        v[i] = *(const float4*)(p + (l + 32 * i) * 4);
        s  += v[i].x + v[i].y + v[i].z + v[i].w;
        q2 += v[i].x*v[i].x + v[i].y*v[i].y + v[i].z*v[i].z + v[i].w*v[i].w;
    }
    #pragma unroll
    for (int off = 16; off; off >>= 1) {
        s  += __shfl_xor_sync(0xffffffffu, s, off);
        q2 += __shfl_xor_sync(0xffffffffu, q2, off);
    }
    float mean = s * (1.f / 1024.f);
    float var = q2 * (1.f / 1024.f) - mean * mean;
    float inv = rsqrtf(var + 1e-5f);
    #pragma unroll
    for (int i = 0; i < 8; i++) {
        int c = (l + 32 * i) * 4;
        float4 w4 = *(const float4*)(w + c);
        float4 g4 = *(const float4*)(bgam + c);
        float4 o;
        o.x = (v[i].x - mean) * inv * w4.x + g4.x;
        o.y = (v[i].y - mean) * inv * w4.y + g4.y;
        o.z = (v[i].z - mean) * inv * w4.z + g4.z;
        o.w = (v[i].w - mean) * inv * w4.w + g4.w;
        *(float4*)(p + c) = o;
    }
}

// ---------------- launch ----------------
extern "C" void kernel_launch(void* const* d_in, const int* in_sizes, int n_in,
                              void* d_out, int out_size) {
    const float* hs   = (const float*)d_in[0];
    const float* mask = (const float*)d_in[1];
    const float* Wq   = (const float*)d_in[2];
    const float* bq   = (const float*)d_in[3];
    const float* Wk   = (const float*)d_in[4];
    const float* bk   = (const float*)d_in[5];
    const float* Wv   = (const float*)d_in[6];
    const float* bv   = (const float*)d_in[7];
    const float* Wo   = (const float*)d_in[8];
    const float* bo   = (const float*)d_in[9];
    // d_in[10..13]: Wp1,bp1,Wp2,bp2 — dead (one_hot(argmax).sum() == 1)
    const float* lnw  = (const float*)d_in[14];
    const float* lnb  = (const float*)d_in[15];
    float* out = (float*)d_out;

    static cudaStream_t st1 = nullptr, st2 = nullptr;
    static cudaEvent_t e0 = nullptr, e_tr = nullptr, e_f2 = nullptr, e_z = nullptr;
    if (!st1) {   // created on the uncaptured correctness call; reused in capture
        cudaStreamCreateWithFlags(&st1, cudaStreamNonBlocking);
        cudaStreamCreateWithFlags(&st2, cudaStreamNonBlocking);
        cudaEventCreateWithFlags(&e0,   cudaEventDisableTiming);
        cudaEventCreateWithFlags(&e_tr, cudaEventDisableTiming);
        cudaEventCreateWithFlags(&e_f2, cudaEventDisableTiming);
        cudaEventCreateWithFlags(&e_z,  cudaEventDisableTiming);
        cudaFuncSetAttribute(k_qkm, cudaFuncAttributeMaxDynamicSharedMemorySize, 149504);
        cudaFuncSetAttribute(k_Tg, cudaFuncAttributeMaxDynamicSharedMemorySize,
                             2 * 128 * PAD * 2);
        cudaFuncSetAttribute(k_comb, cudaFuncAttributeMaxDynamicSharedMemorySize,
                             2 * 128 * PADC * 2);
    }

    // fork: hs transpose runs parallel to wbar-fold + qkm
    cudaEventRecord(e0, 0);
    cudaStreamWaitEvent(st1, e0, 0);
    k_tr<<<dim3(Sn / 64, Hn / 32, Bn), 256, 0, st1>>>(hs);
    cudaEventRecord(e_tr, st1);

    k_bar<<<128, 256>>>(Wq, Wk, bq, bk);
    k_qkm<<<(Bn * Sn) / 32, 256, 149504>>>(hs, mask);

    // fork: z column-sums run parallel to T-GEMM
    cudaEventRecord(e_f2, 0);
    cudaStreamWaitEvent(st2, e_f2, 0);
    k_z<<<dim3(KT, Bn), 128, 0, st2>>>();
    cudaEventRecord(e_z, st2);

    cudaStreamWaitEvent(0, e_tr, 0);
    k_Tg<<<dim3(Hn / 128, KSn, Bn), 256, 2 * 128 * PAD * 2>>>();
    k_Tred<<<(Bn * Hn * KT) / 1024, 256>>>();
    cudaStreamWaitEvent(0, e_z, 0);
    k_U<<<dim3(BHn, 4), 256>>>(Wv, bv, Wo);
    k_comb<<<dim3(Hn / 128, (Bn * Sn) / 128), 256, 2 * 128 * PADC * 2>>>(bo, hs, out);
    k_ln<<<(Bn * Sn) / 8, 256>>>(out, lnw, lnb);
}

// round 10
// speedup vs baseline: 1.4779x; 1.4779x over previous
#include <cuda_runtime.h>
#include <cuda_bf16.h>
#include <math.h>
#include <stdint.h>

// Problem dims (fixed by setup_inputs)
#define Bn 2
#define Sn 2048
#define Hn 1024
#define NHn 16
#define BHn 32        // Bn*NHn
#define NT 8          // series terms n=0..7
#define KT 128        // NHn*NT — GEMM N/K
#define KSn 8         // k-split chunks for k_Tg (8 x 256)

// ---------------- scratch (device globals; no allocations allowed) ----------
__device__ float g_wbar[32 * Hn];
__device__ float g_bbar[32];
__device__ float g_qm[BHn * Sn];                        // [bh][s]
__device__ __align__(16) __nv_bfloat16 g_Pt[Bn * KT * Sn];   // [b][col][k] bf16
__device__ __align__(16) __nv_bfloat16 g_hsT[(size_t)Bn * Hn * Sn]; // [b][j][k] bf16
__device__ float g_Tp[KSn * Bn * Hn * KT];              // partial T fp32
__device__ float g_T[Bn * Hn * KT];                     // [b][j][col]
__device__ float g_z[Bn * KT];                          // [b][h*8+n]
__device__ __align__(16) __nv_bfloat16 g_Ut[Bn * Hn * KT];   // [b][e][col] bf16

__constant__ float c_invf[NT] = {1.f, 1.f, 0.5f, 1.f/6.f, 1.f/24.f, 1.f/120.f,
                                 1.f/720.f, 1.f/5040.f};

// ---------------- warp-level bf16 MMA (sm_80+ baseline; ok on sm_103) -------
__device__ __forceinline__ void mma16816(float* d, const uint32_t* a, const uint32_t* b) {
    asm volatile(
        "mma.sync.aligned.m16n8k16.row.col.f32.bf16.bf16.f32 "
        "{%0,%1,%2,%3}, {%4,%5,%6,%7}, {%8,%9}, {%0,%1,%2,%3};"
        : "+f"(d[0]), "+f"(d[1]), "+f"(d[2]), "+f"(d[3])
        : "r"(a[0]), "r"(a[1]), "r"(a[2]), "r"(a[3]), "r"(b[0]), "r"(b[1]));
}
__device__ __forceinline__ uint32_t bf2u(float a, float b) {
    __nv_bfloat162 h2;
    h2.x = __float2bfloat16_rn(a);
    h2.y = __float2bfloat16_rn(b);
    return *(uint32_t*)&h2;
}

// ---------------- K1: fold Wq/Wk rows into per-head means ----------------
__global__ void k_bar(const float* __restrict__ Wq, const float* __restrict__ Wk,
                      const float* __restrict__ bq, const float* __restrict__ bk) {
    int idx = blockIdx.x * blockDim.x + threadIdx.x;
    if (idx < 32 * Hn) {
        int o = idx >> 10, k = idx & (Hn - 1);
        const float* W = (o < 16) ? Wq : Wk;
        int h = o & 15;
        float s = 0.f;
        #pragma unroll 4
        for (int d = 0; d < 64; d++) s += W[(h * 64 + d) * Hn + k];
        g_wbar[o * Hn + k] = s * (1.f / 64.f);
    }
    if (idx < 32) {
        const float* bb = (idx < 16) ? bq : bk;
        int h = idx & 15;
        float s = 0.f;
        for (int d = 0; d < 64; d++) s += bb[h * 64 + d];
        g_bbar[idx] = s * (1.f / 64.f);
    }
}

// ---------------- K2: qm/km via mma.sync, chunked K (32 rows/block) ---------
// smem: sW bf16[32][1032] staged once; sA bf16[32][136] per 128-k chunk.
#define QPW 1032
#define QPA 136
__global__ void __launch_bounds__(256) k_qkm(const float* __restrict__ hs,
                                             const float* __restrict__ mask) {
    extern __shared__ __align__(16) char qsm[];
    __nv_bfloat16* sW = (__nv_bfloat16*)qsm;                 // 66048 B
    __nv_bfloat16* sA = (__nv_bfloat16*)(qsm + 66048);       // 8704 B

    int t = threadIdx.x;
    int rb = blockIdx.x * 32;

    // stage wbar (fp32 -> bf16), whole 32x1024 once
    {
        int row = t >> 3, cb = (t & 7) * 128;
        const float* wrow = g_wbar + (size_t)row * Hn + cb;
        #pragma unroll
        for (int q = 0; q < 32; q += 2) {
            float4 v0 = *(const float4*)(wrow + q * 4);
            float4 v1 = *(const float4*)(wrow + q * 4 + 4);
            *(uint4*)&sW[row * QPW + cb + q * 4] =
                make_uint4(bf2u(v0.x, v0.y), bf2u(v0.z, v0.w),
                           bf2u(v1.x, v1.y), bf2u(v1.z, v1.w));
        }
    }

    int wid = t >> 5, lane = t & 31, g = lane >> 2, tg = lane & 3;
    int wm = wid & 1, wn = wid >> 1;             // 2 m-tiles x 4 n-tiles
    int r0 = wm * 16 + g;
    float acc[4] = {};

    int arow = t >> 3, acb = (t & 7) * 16;       // A staging: 16 cols/thread
    const float* hrow = hs + (size_t)(rb + arow) * Hn + acb;

    for (int c = 0; c < 8; c++) {                // 8 chunks of 128 k
        __syncthreads();                         // sA free (and sW ready on c=0)
        {
            float4 v0 = *(const float4*)(hrow + c * 128 + 0);
            float4 v1 = *(const float4*)(hrow + c * 128 + 4);
            float4 v2 = *(const float4*)(hrow + c * 128 + 8);
            float4 v3 = *(const float4*)(hrow + c * 128 + 12);
            *(uint4*)&sA[arow * QPA + acb + 0] =
                make_uint4(bf2u(v0.x, v0.y), bf2u(v0.z, v0.w),
                           bf2u(v1.x, v1.y), bf2u(v1.z, v1.w));
            *(uint4*)&sA[arow * QPA + acb + 8] =
                make_uint4(bf2u(v2.x, v2.y), bf2u(v2.z, v2.w),
                           bf2u(v3.x, v3.y), bf2u(v3.z, v3.w));
        }
        __syncthreads();
        #pragma unroll
        for (int ks = 0; ks < 8; ks++) {
            int k0 = ks * 16;
            int kg = c * 128 + k0;
            uint32_t a[4];
            a[0] = *(const uint32_t*)(sA + r0 * QPA + k0 + 2 * tg);
            a[1] = *(const uint32_t*)(sA + (r0 + 8) * QPA + k0 + 2 * tg);
            a[2] = *(const uint32_t*)(sA + r0 * QPA + k0 + 8 + 2 * tg);
            a[3] = *(const uint32_t*)(sA + (r0 + 8) * QPA + k0 + 8 + 2 * tg);
            int n = wn * 8 + g;
            uint32_t bb[2];
            bb[0] = *(const uint32_t*)(sW + n * QPW + kg + 2 * tg);
            bb[1] = *(const uint32_t*)(sW + n * QPW + kg + 8 + 2 * tg);
            mma16816(acc, a, bb);
        }
    }

    // epilogue: this lane owns rows {r0, r0+8}, cols {o0, o0+1}
    int o0 = wn * 8 + 2 * tg;
    #pragma unroll
    for (int rr = 0; rr < 2; rr++) {
        int rg = rb + r0 + rr * 8;
        int b = rg >> 11, s = rg & (Sn - 1);
        float v0 = acc[rr * 2 + 0] + g_bbar[o0];
        float v1 = acc[rr * 2 + 1] + g_bbar[o0 + 1];
        if (o0 < 16) {
            g_qm[(b * NHn + o0) * Sn + s] = v0;
            g_qm[(b * NHn + o0 + 1) * Sn + s] = v1;
        } else {
            float mk = (mask[b * Sn + s] > 0.f) ? 1.f : 0.f;
            int h0 = o0 - 16;
            __nv_bfloat16* d0 = g_Pt + (size_t)(b * KT + h0 * 8) * Sn + s;
            __nv_bfloat16* d1 = g_Pt + (size_t)(b * KT + (h0 + 1) * 8) * Sn + s;
            float p0 = mk, p1 = mk;
            #pragma unroll
            for (int n = 0; n < NT; n++) {
                d0[(size_t)n * Sn] = __float2bfloat16_rn(p0);
                d1[(size_t)n * Sn] = __float2bfloat16_rn(p1);
                p0 *= v0; p1 *= v1;
            }
        }
    }
}

// ---------------- K3: transpose hs -> g_hsT bf16 [b][j][k] ----------------
__global__ void __launch_bounds__(256) k_tr(const float* __restrict__ hs) {
    __shared__ float sm[64][33];
    int t = threadIdx.x;
    int k0 = blockIdx.x * 64, j0 = blockIdx.y * 32, b = blockIdx.z;
    #pragma unroll
    for (int i = 0; i < 2; i++) {
        int idx = t + 256 * i;
        int k = idx >> 3, jq = (idx & 7) * 4;
        float4 v = *(const float4*)&hs[(size_t)(b * Sn + k0 + k) * Hn + j0 + jq];
        sm[k][jq + 0] = v.x; sm[k][jq + 1] = v.y; sm[k][jq + 2] = v.z; sm[k][jq + 3] = v.w;
    }
    __syncthreads();
    int jj = t >> 3, c = t & 7;
    uint32_t w[4];
    #pragma unroll
    for (int q = 0; q < 4; q++)
        w[q] = bf2u(sm[c * 8 + q * 2 + 0][jj], sm[c * 8 + q * 2 + 1][jj]);
    *(uint4*)(g_hsT + ((size_t)(b * Hn + j0 + jj)) * Sn + k0 + c * 8) =
        make_uint4(w[0], w[1], w[2], w[3]);
}

// ---------------- K4: z[b][col] = sum_k Pt[b][col][k] (8 cols/block) --------
__global__ void __launch_bounds__(256) k_z() {
    int t = threadIdx.x;
    int w = t >> 5, l = t & 31;
    int col = blockIdx.x * 8 + w, b = blockIdx.y;
    const __nv_bfloat16* src = g_Pt + (size_t)(b * KT + col) * Sn;
    float s = 0.f;
    #pragma unroll
    for (int i = 0; i < 8; i++) {
        uint4 v = *(const uint4*)(src + (l + 32 * i) * 8);
        uint32_t u[4] = {v.x, v.y, v.z, v.w};
        #pragma unroll
        for (int q = 0; q < 4; q++) {
            float2 f = __bfloat1622float2(*(__nv_bfloat162*)&u[q]);
            s += f.x + f.y;
        }
    }
    #pragma unroll
    for (int off = 16; off; off >>= 1) s += __shfl_xor_sync(0xffffffffu, s, off);
    if (l == 0) g_z[b * KT + col] = s;
}

// ---------------- K5: T-GEMM via mma.sync: Tp = hsT @ Pt^T (128x128x256) ----
#define PAD 264
__global__ void __launch_bounds__(256) k_Tg() {
    extern __shared__ __align__(16) __nv_bfloat16 smem[];
    __nv_bfloat16* sA = smem;               // [128][264]
    __nv_bfloat16* sB = smem + 128 * PAD;   // [128][264]
    int t = threadIdx.x;
    int jt = blockIdx.x, kc = blockIdx.y, b = blockIdx.z;
    int k0g = kc * 256;

    const __nv_bfloat16* Asrc = g_hsT + ((size_t)(b * Hn + jt * 128)) * Sn + k0g;
    const __nv_bfloat16* Bsrc = g_Pt + ((size_t)(b * KT)) * Sn + k0g;
    #pragma unroll
    for (int i = 0; i < 16; i++) {
        int idx = t + 256 * i;
        int m = idx >> 5, c = idx & 31;
        *(uint4*)(sA + m * PAD + c * 8) = *(const uint4*)(Asrc + (size_t)m * Sn + c * 8);
        *(uint4*)(sB + m * PAD + c * 8) = *(const uint4*)(Bsrc + (size_t)m * Sn + c * 8);
    }
    __syncthreads();

    int wid = t >> 5, lane = t & 31;
    int wm = wid >> 1, wn = wid & 1;
    int R = wm * 32, Cb = wn * 64;
    int g = lane >> 2, tg = lane & 3;

    float acc[2][8][4];
    #pragma unroll
    for (int mi = 0; mi < 2; mi++)
        #pragma unroll
        for (int ni = 0; ni < 8; ni++)
            #pragma unroll
            for (int q = 0; q < 4; q++) acc[mi][ni][q] = 0.f;

    #pragma unroll 4
    for (int ks = 0; ks < 16; ks++) {
        int k0 = ks * 16;
        uint32_t a[2][4];
        #pragma unroll
        for (int mi = 0; mi < 2; mi++) {
            int r0 = R + mi * 16 + g;
            a[mi][0] = *(const uint32_t*)(sA + r0 * PAD + k0 + 2 * tg);
            a[mi][1] = *(const uint32_t*)(sA + (r0 + 8) * PAD + k0 + 2 * tg);
            a[mi][2] = *(const uint32_t*)(sA + r0 * PAD + k0 + 8 + 2 * tg);
            a[mi][3] = *(const uint32_t*)(sA + (r0 + 8) * PAD + k0 + 8 + 2 * tg);
        }
        #pragma unroll
        for (int ni = 0; ni < 8; ni++) {
            int n = Cb + ni * 8 + g;
            uint32_t bb[2];
            bb[0] = *(const uint32_t*)(sB + n * PAD + k0 + 2 * tg);
            bb[1] = *(const uint32_t*)(sB + n * PAD + k0 + 8 + 2 * tg);
            mma16816(acc[0][ni], a[0], bb);
            mma16816(acc[1][ni], a[1], bb);
        }
    }

    #pragma unroll
    for (int mi = 0; mi < 2; mi++) {
        int j = jt * 128 + R + mi * 16 + g;
        float* base = g_Tp + ((size_t)((kc * Bn + b) * Hn + j)) * KT;
        #pragma unroll
        for (int ni = 0; ni < 8; ni++) {
            int col = Cb + ni * 8 + 2 * tg;
            *(float2*)(base + col) = make_float2(acc[mi][ni][0], acc[mi][ni][1]);
            *(float2*)(base + 8 * KT + col) = make_float2(acc[mi][ni][2], acc[mi][ni][3]);
        }
    }
}

// ---------------- K6: reduce T partials (deterministic, float4) -------------
__global__ void __launch_bounds__(256) k_Tred() {
    int idx = blockIdx.x * 256 + threadIdx.x;
    const float4* src = (const float4*)g_Tp;
    float4 s = src[idx];
    #pragma unroll
    for (int kc = 1; kc < KSn; kc++) {
        float4 v = src[(size_t)kc * (Bn * Hn * KT / 4) + idx];
        s.x += v.x; s.y += v.y; s.z += v.z; s.w += v.w;
    }
    ((float4*)g_T)[idx] = s;
}

// ---------------- K7: Ut[b][e][h*8+n] = bf16(((T@Wv_h^T)+z*bv_h)@Wo_h^T) ----
__global__ void __launch_bounds__(256) k_U(const float* __restrict__ Wv,
                                           const float* __restrict__ bv,
                                           const float* __restrict__ Wo) {
    int bh = blockIdx.x, b = bh >> 4, h = bh & 15;
    int eq = blockIdx.y;
    __shared__ float Ts[NT][Hn];
    __shared__ float Ms[NT][64];
    int t = threadIdx.x;
    #pragma unroll
    for (int i = 0; i < 4; i++) {
        int j = t + 256 * i;
        const float* src = g_T + (((size_t)(b * Hn + j)) << 7) + h * 8;
        float4 v0 = *(const float4*)src;
        float4 v1 = *(const float4*)(src + 4);
        Ts[0][j] = v0.x; Ts[1][j] = v0.y; Ts[2][j] = v0.z; Ts[3][j] = v0.w;
        Ts[4][j] = v1.x; Ts[5][j] = v1.y; Ts[6][j] = v1.z; Ts[7][j] = v1.w;
    }
    float zl[NT];
    #pragma unroll
    for (int n = 0; n < NT; n++) zl[n] = g_z[b * KT + h * 8 + n];
    __syncthreads();

    int d = t >> 2, part = t & 3;
    float pn[NT] = {};
    const float* wv = Wv + (size_t)(h * 64 + d) * Hn + part * 256;
    for (int jj = 0; jj < 256; jj += 4) {
        float4 w4 = *(const float4*)(wv + jj);
        int jb = part * 256 + jj;
        #pragma unroll
        for (int n = 0; n < NT; n++) {
            float4 t4 = *(const float4*)&Ts[n][jb];
            pn[n] += w4.x * t4.x + w4.y * t4.y + w4.z * t4.z + w4.w * t4.w;
        }
    }
    #pragma unroll
    for (int n = 0; n < NT; n++) {
        pn[n] += __shfl_xor_sync(0xffffffffu, pn[n], 1);
        pn[n] += __shfl_xor_sync(0xffffffffu, pn[n], 2);
    }
    if (part == 0) {
        float bvd = bv[h * 64 + d];
        #pragma unroll
        for (int n = 0; n < NT; n++) Ms[n][d] = pn[n] + zl[n] * bvd;
    }
    __syncthreads();

    int e = eq * 256 + t;
    float u[NT] = {};
    const float* wo = Wo + (size_t)e * Hn + h * 64;
    #pragma unroll 4
    for (int dd = 0; dd < 64; dd += 4) {
        float4 w4 = *(const float4*)(wo + dd);
        #pragma unroll
        for (int n = 0; n < NT; n++)
            u[n] += w4.x * Ms[n][dd] + w4.y * Ms[n][dd+1]
                  + w4.z * Ms[n][dd+2] + w4.w * Ms[n][dd+3];
    }
    uint32_t w[4];
    #pragma unroll
    for (int q = 0; q < 4; q++)
        w[q] = bf2u(u[q * 2 + 0], u[q * 2 + 1]);
    *(uint4*)(g_Ut + ((size_t)(b * Hn + e)) * KT + h * 8) = make_uint4(w[0], w[1], w[2], w[3]);
}

// ---------------- K8: out = coef@Ut^T + bo + hs via mma.sync (128x128x128) --
#define PADC 136
__global__ void __launch_bounds__(256) k_comb(const float* __restrict__ bo,
                                              const float* __restrict__ hs,
                                              float* __restrict__ out) {
    extern __shared__ __align__(16) __nv_bfloat16 smemc[];
    __nv_bfloat16* sA = smemc;                // coef [128][136]
    __nv_bfloat16* sB = smemc + 128 * PADC;   // Ut   [128][136]
    __shared__ float zs[KT];

    int t = threadIdx.x;
    int bn = blockIdx.x, bm = blockIdx.y;
    int b = bm >> 4;
    int sbase = (bm & 15) * 128;

    if (t < KT) zs[t] = g_z[b * KT + t];

    #pragma unroll
    for (int i = 0; i < 8; i++) {
        int idx = t + 256 * i;
        int row = idx >> 4, c = idx & 15;
        *(uint4*)(sB + row * PADC + c * 8) =
            *(const uint4*)(g_Ut + ((size_t)(b * Hn + bn * 128 + row)) * KT + c * 8);
    }
    __syncthreads();   // zs visible

    {
        int m = t >> 1, hbase = (t & 1) * 8;
        int s = sbase + m;
        #pragma unroll
        for (int hh = 0; hh < 8; hh++) {
            int h = hbase + hh;
            float a = g_qm[(size_t)(b * NHn + h) * Sn + s];
            float c[NT], p = 1.f, den = 0.f;
            #pragma unroll
            for (int n = 0; n < NT; n++) {
                c[n] = p * c_invf[n];
                den += c[n] * zs[h * 8 + n];
                p *= a;
            }
            float inv = (den > 0.f) ? 1.f / den : 0.f;
            uint32_t wv[4];
            #pragma unroll
            for (int q = 0; q < 4; q++)
                wv[q] = bf2u(c[q * 2 + 0] * inv, c[q * 2 + 1] * inv);
            *(uint4*)(sA + m * PADC + h * 8) = make_uint4(wv[0], wv[1], wv[2], wv[3]);
        }
    }
    __syncthreads();

    int wid = t >> 5, lane = t & 31;
    int wm = wid >> 1, wn = wid & 1;
    int R = wm * 32, Cb = wn * 64;
    int g = lane >> 2, tg = lane & 3;

    float acc[2][8][4];
    #pragma unroll
    for (int mi = 0; mi < 2; mi++)
        #pragma unroll
        for (int ni = 0; ni < 8; ni++)
            #pragma unroll
            for (int q = 0; q < 4; q++) acc[mi][ni][q] = 0.f;

    #pragma unroll
    for (int ks = 0; ks < 8; ks++) {
        int k0 = ks * 16;
        uint32_t a[2][4];
        #pragma unroll
        for (int mi = 0; mi < 2; mi++) {
            int r0 = R + mi * 16 + g;
            a[mi][0] = *(const uint32_t*)(sA + r0 * PADC + k0 + 2 * tg);
            a[mi][1] = *(const uint32_t*)(sA + (r0 + 8) * PADC + k0 + 2 * tg);
            a[mi][2] = *(const uint32_t*)(sA + r0 * PADC + k0 + 8 + 2 * tg);
            a[mi][3] = *(const uint32_t*)(sA + (r0 + 8) * PADC + k0 + 8 + 2 * tg);
        }
        #pragma unroll
        for (int ni = 0; ni < 8; ni++) {
            int n = Cb + ni * 8 + g;
            uint32_t bb[2];
            bb[0] = *(const uint32_t*)(sB + n * PADC + k0 + 2 * tg);
            bb[1] = *(const uint32_t*)(sB + n * PADC + k0 + 8 + 2 * tg);
            mma16816(acc[0][ni], a[0], bb);
            mma16816(acc[1][ni], a[1], bb);
        }
    }

    #pragma unroll
    for (int mi = 0; mi < 2; mi++) {
        #pragma unroll
        for (int half = 0; half < 2; half++) {
            int row = bm * 128 + R + mi * 16 + g + half * 8;
            const float* hp = hs + (size_t)row * Hn;
            float* op = out + (size_t)row * Hn;
            #pragma unroll
            for (int ni = 0; ni < 8; ni++) {
                int col = bn * 128 + Cb + ni * 8 + 2 * tg;
                float2 h2 = *(const float2*)(hp + col);
                float2 b2 = *(const float2*)(bo + col);
                float d0 = acc[mi][ni][half * 2 + 0] + h2.x + b2.x;
                float d1 = acc[mi][ni][half * 2 + 1] + h2.y + b2.y;
                *(float2*)(op + col) = make_float2(d0, d1);
            }
        }
    }
}

// ---------------- K9: LayerNorm, warp-per-row (8 rows/block) ----------------
__global__ void __launch_bounds__(256) k_ln(float* __restrict__ x,
                                            const float* __restrict__ w,
                                            const float* __restrict__ bgam) {
    int wrp = threadIdx.x >> 5, l = threadIdx.x & 31;
    int row = blockIdx.x * 8 + wrp;
    float* p = x + (size_t)row * Hn;
    float4 v[8];
    float s = 0.f, q2 = 0.f;
    #pragma unroll
    for (int i = 0; i < 8; i++) {
        v[i] = *(const float4*)(p + (l + 32 * i) * 4);
        s  += v[i].x + v[i].y + v[i].z + v[i].w;
        q2 += v[i].x*v[i].x + v[i].y*v[i].y + v[i].z*v[i].z + v[i].w*v[i].w;
    }
    #pragma unroll
    for (int off = 16; off; off >>= 1) {
        s  += __shfl_xor_sync(0xffffffffu, s, off);
        q2 += __shfl_xor_sync(0xffffffffu, q2, off);
    }
    float mean = s * (1.f / 1024.f);
    float var = q2 * (1.f / 1024.f) - mean * mean;
    float inv = rsqrtf(var + 1e-5f);
    #pragma unroll
    for (int i = 0; i < 8; i++) {
        int c = (l + 32 * i) * 4;
        float4 w4 = *(const float4*)(w + c);
        float4 g4 = *(const float4*)(bgam + c);
        float4 o;
        o.x = (v[i].x - mean) * inv * w4.x + g4.x;
        o.y = (v[i].y - mean) * inv * w4.y + g4.y;
        o.z = (v[i].z - mean) * inv * w4.z + g4.z;
        o.w = (v[i].w - mean) * inv * w4.w + g4.w;
        *(float4*)(p + c) = o;
    }
}

// ---------------- launch (single stream, R8 order) ----------------
extern "C" void kernel_launch(void* const* d_in, const int* in_sizes, int n_in,
                              void* d_out, int out_size) {
    const float* hs   = (const float*)d_in[0];
    const float* mask = (const float*)d_in[1];
    const float* Wq   = (const float*)d_in[2];
    const float* bq   = (const float*)d_in[3];
    const float* Wk   = (const float*)d_in[4];
    const float* bk   = (const float*)d_in[5];
    const float* Wv   = (const float*)d_in[6];
    const float* bv   = (const float*)d_in[7];
    const float* Wo   = (const float*)d_in[8];
    const float* bo   = (const float*)d_in[9];
    // d_in[10..13]: Wp1,bp1,Wp2,bp2 — dead (one_hot(argmax).sum() == 1)
    const float* lnw  = (const float*)d_in[14];
    const float* lnb  = (const float*)d_in[15];
    float* out = (float*)d_out;

    static int s_attr_done = 0;
    if (!s_attr_done) {
        cudaFuncSetAttribute(k_qkm, cudaFuncAttributeMaxDynamicSharedMemorySize, 74752);
        cudaFuncSetAttribute(k_Tg, cudaFuncAttributeMaxDynamicSharedMemorySize,
                             2 * 128 * PAD * 2);
        cudaFuncSetAttribute(k_comb, cudaFuncAttributeMaxDynamicSharedMemorySize,
                             2 * 128 * PADC * 2);
        s_attr_done = 1;
    }

    k_bar<<<128, 256>>>(Wq, Wk, bq, bk);
    k_qkm<<<(Bn * Sn) / 32, 256, 74752>>>(hs, mask);
    k_tr<<<dim3(Sn / 64, Hn / 32, Bn), 256>>>(hs);
    k_z<<<dim3(KT / 8, Bn), 256>>>();
    k_Tg<<<dim3(Hn / 128, KSn, Bn), 256, 2 * 128 * PAD * 2>>>();
    k_Tred<<<(Bn * Hn * KT) / 1024, 256>>>();
    k_U<<<dim3(BHn, 4), 256>>>(Wv, bv, Wo);
    k_comb<<<dim3(Hn / 128, (Bn * Sn) / 128), 256, 2 * 128 * PADC * 2>>>(bo, hs, out);
    k_ln<<<(Bn * Sn) / 8, 256>>>(out, lnw, lnb);
}